// round 3
// baseline (speedup 1.0000x reference)
#include <cuda_runtime.h>
#include <math.h>

#define Nn   100000
#define Ee   3200000
#define INC  500
#define HIDC 256
#define OUTC 64
#define KHOP 10
#define NB_SCAN 98   // ceil(100000/1024)

// ---------------- scratch (static device globals; no allocation) ----------------
__device__ __align__(16) float g_H[(size_t)Nn * HIDC];     // hidden activations  [N,256]
__device__ __align__(16) float g_Xa[(size_t)Nn * OUTC];    // ping
__device__ __align__(16) float g_Xb[(size_t)Nn * OUTC];    // pong
__device__ __align__(16) float g_dinv[Nn];
__device__ __align__(16) int   g_cnt[Nn];
__device__ __align__(16) int   g_rowptr[Nn + 2];
__device__ __align__(16) int   g_cursor[Nn];
__device__ __align__(16) int   g_src[Ee];
__device__ __align__(16) float g_wn[Ee];
__device__ __align__(16) int   g_bsums[NB_SCAN];
__device__ int g_is64;

// ---------------- edge dtype detection ----------------
// int64 edge values are < 2^31, so every odd 32-bit word is 0. For int32 edge
// data the odd words are real node ids (~0 probability all zero). 1 thread.
__global__ void k_detect(const int* __restrict__ ei32) {
    int is64 = 1;
    for (int i = 1; i < 64; i += 2)
        if (ei32[i] != 0) { is64 = 0; break; }
    g_is64 = is64;
}

// read edge e's (row, col) as int32 words, layout-dependent
__device__ __forceinline__ void load_edge(const int* __restrict__ ei32, int e,
                                          int& r, int& c) {
    if (g_is64) {
        r = ei32[(size_t)2 * e];                       // low word of ei64[e]
        c = ei32[(size_t)2 * ((size_t)Ee + e)];        // low word of ei64[Ee+e]
    } else {
        r = ei32[e];
        c = ei32[(size_t)Ee + e];
    }
    // trap-proof clamp (values are in-range per problem spec)
    r = min(max(r, 0), Nn - 1);
    c = min(max(c, 0), Nn - 1);
}

// ---------------- degree / CSR construction ----------------
__global__ void k_zero_cnt() {
    int i = blockIdx.x * blockDim.x + threadIdx.x;
    if (i < Nn) g_cnt[i] = 0;
}

__global__ void k_count(const int* __restrict__ ei32) {
    int e = blockIdx.x * blockDim.x + threadIdx.x;
    if (e >= Ee) return;
    int r, c;
    load_edge(ei32, e, r, c);
    if (r != c) atomicAdd(&g_cnt[c], 1);
}

__global__ void k_dinv() {
    int i = blockIdx.x * blockDim.x + threadIdx.x;
    if (i < Nn) g_dinv[i] = rsqrtf((float)(g_cnt[i] + 1));
}

__global__ void k_scan1() {
    __shared__ int s[1024];
    int t = threadIdx.x;
    int i = blockIdx.x * 1024 + t;
    int v = (i < Nn) ? g_cnt[i] : 0;
    s[t] = v;
    __syncthreads();
    for (int o = 1; o < 1024; o <<= 1) {
        int y = (t >= o) ? s[t - o] : 0;
        __syncthreads();
        s[t] += y;
        __syncthreads();
    }
    int incl = s[t];
    if (i < Nn) g_rowptr[i] = incl - v;   // local exclusive
    if (t == 1023) g_bsums[blockIdx.x] = incl;
}

__global__ void k_scan2() {
    int run = 0;
    for (int b = 0; b < NB_SCAN; b++) { int x = g_bsums[b]; g_bsums[b] = run; run += x; }
    g_rowptr[Nn] = run;
}

__global__ void k_scan3() {
    int i = blockIdx.x * 1024 + threadIdx.x;
    if (i < Nn) {
        int v = g_rowptr[i] + g_bsums[blockIdx.x];
        g_rowptr[i] = v;
        g_cursor[i] = v;
    }
}

__global__ void k_fill(const int* __restrict__ ei32) {
    int e = blockIdx.x * blockDim.x + threadIdx.x;
    if (e >= Ee) return;
    int r, c;
    load_edge(ei32, e, r, c);
    if (r != c) {
        int pos = atomicAdd(&g_cursor[c], 1);
        pos = min(max(pos, 0), Ee - 1);
        g_src[pos] = r;
        g_wn[pos]  = g_dinv[r] * g_dinv[c];
    }
}

// Canonicalize per-segment order (insertion sort by src) so float sums are
// bitwise deterministic across replays despite atomic fill ordering.
__global__ void k_sortseg() {
    int n = blockIdx.x * blockDim.x + threadIdx.x;
    if (n >= Nn) return;
    int e0 = g_rowptr[n], e1 = g_rowptr[n + 1];
    for (int i = e0 + 1; i < e1; i++) {
        int s = g_src[i]; float w = g_wn[i];
        int j = i - 1;
        while (j >= e0 && g_src[j] > s) {
            g_src[j + 1] = g_src[j]; g_wn[j + 1] = g_wn[j]; j--;
        }
        g_src[j + 1] = s; g_wn[j + 1] = w;
    }
}

// ---------------- fp32 tiled GEMM: C[m,n] = sum_k A[m,k]*B[n,k] + bias[n] ----------------
// BM=128, BN=64, BK=16, 256 threads, each computes 8x4.
// mode 0: A = Aext (node_feat), C = g_H ; mode 1: A = g_H, C = g_Xa
__global__ __launch_bounds__(256)
void k_gemm(const float* __restrict__ Aext, const float* __restrict__ B,
            const float* __restrict__ bias,
            int M, int Kd, int Ncols, int relu, int mode)
{
    __shared__ __align__(16) float As[16][132];
    __shared__ __align__(16) float Bs[16][68];
    const float* A = (mode == 0) ? Aext : g_H;
    float*       C = (mode == 0) ? g_H  : g_Xa;

    int t  = threadIdx.x;
    int m0 = blockIdx.x * 128;
    int n0 = blockIdx.y * 64;
    int ty = t >> 4, tx = t & 15;

    float acc[8][4];
    #pragma unroll
    for (int i = 0; i < 8; i++)
        #pragma unroll
        for (int j = 0; j < 4; j++) acc[i][j] = 0.f;

    for (int k0 = 0; k0 < Kd; k0 += 16) {
        #pragma unroll
        for (int r = 0; r < 2; r++) {
            int idx = t + r * 256;
            int row = idx >> 2;
            int kc  = (idx & 3) << 2;
            float4 v = make_float4(0.f, 0.f, 0.f, 0.f);
            int gm = m0 + row, gk = k0 + kc;
            if (gm < M && gk < Kd)
                v = *reinterpret_cast<const float4*>(A + (size_t)gm * Kd + gk);
            As[kc + 0][row] = v.x; As[kc + 1][row] = v.y;
            As[kc + 2][row] = v.z; As[kc + 3][row] = v.w;
        }
        {
            int row = t >> 2, kc = (t & 3) << 2;
            float4 v = make_float4(0.f, 0.f, 0.f, 0.f);
            int gn = n0 + row, gk = k0 + kc;
            if (gk < Kd)
                v = *reinterpret_cast<const float4*>(B + (size_t)gn * Kd + gk);
            Bs[kc + 0][row] = v.x; Bs[kc + 1][row] = v.y;
            Bs[kc + 2][row] = v.z; Bs[kc + 3][row] = v.w;
        }
        __syncthreads();

        #pragma unroll
        for (int k = 0; k < 16; k++) {
            float4 a0 = *reinterpret_cast<const float4*>(&As[k][ty * 8]);
            float4 a1 = *reinterpret_cast<const float4*>(&As[k][ty * 8 + 4]);
            float4 bv = *reinterpret_cast<const float4*>(&Bs[k][tx * 4]);
            float a[8] = {a0.x, a0.y, a0.z, a0.w, a1.x, a1.y, a1.z, a1.w};
            float b[4] = {bv.x, bv.y, bv.z, bv.w};
            #pragma unroll
            for (int i = 0; i < 8; i++)
                #pragma unroll
                for (int j = 0; j < 4; j++)
                    acc[i][j] = fmaf(a[i], b[j], acc[i][j]);
        }
        __syncthreads();
    }

    float b0 = bias[n0 + tx * 4 + 0];
    float b1 = bias[n0 + tx * 4 + 1];
    float b2 = bias[n0 + tx * 4 + 2];
    float b3 = bias[n0 + tx * 4 + 3];
    #pragma unroll
    for (int i = 0; i < 8; i++) {
        int gm = m0 + ty * 8 + i;
        if (gm >= M) continue;
        float4 v;
        v.x = acc[i][0] + b0; v.y = acc[i][1] + b1;
        v.z = acc[i][2] + b2; v.w = acc[i][3] + b3;
        if (relu) {
            v.x = fmaxf(v.x, 0.f); v.y = fmaxf(v.y, 0.f);
            v.z = fmaxf(v.z, 0.f); v.w = fmaxf(v.w, 0.f);
        }
        *reinterpret_cast<float4*>(C + (size_t)gm * Ncols + n0 + tx * 4) = v;
    }
}

// ---------------- hop-0 combine: out[n] = sigmoid(x0·pw + pb) * x0 ----------------
__global__ __launch_bounds__(256)
void k_combine0(const float* __restrict__ pw, const float* __restrict__ pb,
                float* __restrict__ out)
{
    int gw = (blockIdx.x * blockDim.x + threadIdx.x) >> 5;
    if (gw >= Nn) return;
    int lane = threadIdx.x & 31;
    const float2* x = reinterpret_cast<const float2*>(g_Xa);
    float2 v = x[gw * 32 + lane];
    float t = v.x * pw[2 * lane] + v.y * pw[2 * lane + 1];
    #pragma unroll
    for (int o = 16; o; o >>= 1) t += __shfl_xor_sync(0xffffffffu, t, o);
    float s = 1.f / (1.f + expf(-(t + pb[0])));
    reinterpret_cast<float2*>(out)[gw * 32 + lane] = make_float2(s * v.x, s * v.y);
}

// ---------------- fused propagation + attention-combine ----------------
// one warp per node; lane handles cols (2l, 2l+1)
__global__ __launch_bounds__(256)
void k_prop(int dir, const float* __restrict__ pw, const float* __restrict__ pb,
            float* __restrict__ out)
{
    int gw = (blockIdx.x * blockDim.x + threadIdx.x) >> 5;
    if (gw >= Nn) return;
    int lane = threadIdx.x & 31;
    const float2* xin = reinterpret_cast<const float2*>(dir ? g_Xb : g_Xa);
    float2*      xout = reinterpret_cast<float2*>(dir ? g_Xa : g_Xb);

    float d  = g_dinv[gw];
    float sw = d * d;
    float2 v = xin[gw * 32 + lane];
    float ax = sw * v.x;
    float ay = sw * v.y;

    int e  = g_rowptr[gw];
    int e1 = g_rowptr[gw + 1];
    for (; e + 4 <= e1; e += 4) {
        int   s0 = g_src[e], s1 = g_src[e + 1], s2 = g_src[e + 2], s3 = g_src[e + 3];
        float w0 = g_wn[e],  w1 = g_wn[e + 1],  w2 = g_wn[e + 2],  w3 = g_wn[e + 3];
        float2 p0 = xin[s0 * 32 + lane];
        float2 p1 = xin[s1 * 32 + lane];
        float2 p2 = xin[s2 * 32 + lane];
        float2 p3 = xin[s3 * 32 + lane];
        ax = fmaf(w0, p0.x, ax); ay = fmaf(w0, p0.y, ay);
        ax = fmaf(w1, p1.x, ax); ay = fmaf(w1, p1.y, ay);
        ax = fmaf(w2, p2.x, ax); ay = fmaf(w2, p2.y, ay);
        ax = fmaf(w3, p3.x, ax); ay = fmaf(w3, p3.y, ay);
    }
    for (; e < e1; e++) {
        int s = g_src[e]; float w = g_wn[e];
        float2 p = xin[s * 32 + lane];
        ax = fmaf(w, p.x, ax); ay = fmaf(w, p.y, ay);
    }

    xout[gw * 32 + lane] = make_float2(ax, ay);

    float t = ax * pw[2 * lane] + ay * pw[2 * lane + 1];
    #pragma unroll
    for (int o = 16; o; o >>= 1) t += __shfl_xor_sync(0xffffffffu, t, o);
    float s = 1.f / (1.f + expf(-(t + pb[0])));

    float2* op = reinterpret_cast<float2*>(out) + gw * 32 + lane;
    float2 cur = *op;
    cur.x += s * ax;
    cur.y += s * ay;
    *op = cur;
}

// ---------------- launch ----------------
extern "C" void kernel_launch(void* const* d_in, const int* in_sizes, int n_in,
                              void* d_out, int out_size)
{
    const float* node_feat = (const float*)d_in[0];
    const int*   ei32      = (const int*)d_in[1];   // int32 words (works for int64 too)
    const float* W1        = (const float*)d_in[2];
    const float* b1        = (const float*)d_in[3];
    const float* W2        = (const float*)d_in[4];
    const float* b2        = (const float*)d_in[5];
    const float* pw        = (const float*)d_in[6];
    const float* pb        = (const float*)d_in[7];
    float*       out       = (float*)d_out;

    const int TB = 256;
    int gN = (Nn + TB - 1) / TB;
    int gE = (Ee + TB - 1) / TB;
    int gW = (Nn * 32 + TB - 1) / TB;   // warp-per-node grids

    // edge dtype detection + CSR build (deterministic after k_sortseg)
    k_detect<<<1, 1>>>(ei32);
    k_zero_cnt<<<gN, TB>>>();
    k_count<<<gE, TB>>>(ei32);
    k_dinv<<<gN, TB>>>();
    k_scan1<<<NB_SCAN, 1024>>>();
    k_scan2<<<1, 1>>>();
    k_scan3<<<NB_SCAN, 1024>>>();
    k_fill<<<gE, TB>>>(ei32);
    k_sortseg<<<gN, TB>>>();

    // MLP: H = relu(node_feat @ W1^T + b1) ; X0 = H @ W2^T + b2
    dim3 g1((Nn + 127) / 128, HIDC / 64);
    k_gemm<<<g1, 256>>>(node_feat, W1, b1, Nn, INC, HIDC, 1, 0);
    dim3 g2((Nn + 127) / 128, OUTC / 64);
    k_gemm<<<g2, 256>>>(node_feat, W2, b2, Nn, HIDC, OUTC, 0, 1);

    // hop 0 combine, then K fused propagate+combine steps
    k_combine0<<<gW, TB>>>(pw, pb, out);
    for (int k = 0; k < KHOP; k++)
        k_prop<<<gW, TB>>>(k & 1, pw, pb, out);
}

// round 4
// speedup vs baseline: 1.1162x; 1.1162x over previous
#include <cuda_runtime.h>
#include <cuda_bf16.h>
#include <math.h>

#define Nn   100000
#define Ee   3200000
#define INC  500
#define KP1  512     // K for GEMM1 padded to 512
#define HIDC 256
#define OUTC 64
#define KHOP 10
#define NB_SCAN 98   // ceil(100000/1024)

// ---------------- scratch (static device globals; no allocation) ----------------
__device__ __align__(16) __nv_bfloat16 g_Ah[(size_t)Nn * KP1];
__device__ __align__(16) __nv_bfloat16 g_Al[(size_t)Nn * KP1];
__device__ __align__(16) __nv_bfloat16 g_W1h[(size_t)HIDC * KP1];
__device__ __align__(16) __nv_bfloat16 g_W1l[(size_t)HIDC * KP1];
__device__ __align__(16) __nv_bfloat16 g_Hh[(size_t)Nn * HIDC];
__device__ __align__(16) __nv_bfloat16 g_Hl[(size_t)Nn * HIDC];
__device__ __align__(16) __nv_bfloat16 g_W2h[(size_t)OUTC * HIDC];
__device__ __align__(16) __nv_bfloat16 g_W2l[(size_t)OUTC * HIDC];
__device__ __align__(16) float g_Xa[(size_t)Nn * OUTC];    // ping
__device__ __align__(16) float g_Xb[(size_t)Nn * OUTC];    // pong
__device__ __align__(16) float g_dinv[Nn];
__device__ __align__(16) int   g_cnt[Nn];
__device__ __align__(16) int   g_rowptr[Nn + 2];
__device__ __align__(16) int   g_cursor[Nn];
__device__ __align__(16) int   g_src[Ee];
__device__ __align__(16) float g_wn[Ee];
__device__ __align__(16) int   g_bsums[NB_SCAN];
__device__ int g_is64;

// ---------------- edge dtype detection (int64 odd words are all zero) ----------------
__global__ void k_detect(const int* __restrict__ ei32) {
    int is64 = 1;
    for (int i = 1; i < 64; i += 2)
        if (ei32[i] != 0) { is64 = 0; break; }
    g_is64 = is64;
}

__device__ __forceinline__ void load_edge(const int* __restrict__ ei32, int e,
                                          int& r, int& c) {
    if (g_is64) {
        r = ei32[(size_t)2 * e];
        c = ei32[(size_t)2 * ((size_t)Ee + e)];
    } else {
        r = ei32[e];
        c = ei32[(size_t)Ee + e];
    }
    r = min(max(r, 0), Nn - 1);
    c = min(max(c, 0), Nn - 1);
}

// ---------------- degree / CSR construction ----------------
__global__ void k_zero_cnt() {
    int i = blockIdx.x * blockDim.x + threadIdx.x;
    if (i < Nn) g_cnt[i] = 0;
}

__global__ void k_count(const int* __restrict__ ei32) {
    int e = blockIdx.x * blockDim.x + threadIdx.x;
    if (e >= Ee) return;
    int r, c;
    load_edge(ei32, e, r, c);
    if (r != c) atomicAdd(&g_cnt[c], 1);
}

__global__ void k_dinv() {
    int i = blockIdx.x * blockDim.x + threadIdx.x;
    if (i < Nn) g_dinv[i] = rsqrtf((float)(g_cnt[i] + 1));
}

__global__ void k_scan1() {
    __shared__ int s[1024];
    int t = threadIdx.x;
    int i = blockIdx.x * 1024 + t;
    int v = (i < Nn) ? g_cnt[i] : 0;
    s[t] = v;
    __syncthreads();
    for (int o = 1; o < 1024; o <<= 1) {
        int y = (t >= o) ? s[t - o] : 0;
        __syncthreads();
        s[t] += y;
        __syncthreads();
    }
    int incl = s[t];
    if (i < Nn) g_rowptr[i] = incl - v;
    if (t == 1023) g_bsums[blockIdx.x] = incl;
}

__global__ void k_scan2() {
    int run = 0;
    for (int b = 0; b < NB_SCAN; b++) { int x = g_bsums[b]; g_bsums[b] = run; run += x; }
    g_rowptr[Nn] = run;
}

__global__ void k_scan3() {
    int i = blockIdx.x * 1024 + threadIdx.x;
    if (i < Nn) {
        int v = g_rowptr[i] + g_bsums[blockIdx.x];
        g_rowptr[i] = v;
        g_cursor[i] = v;
    }
}

__global__ void k_fill(const int* __restrict__ ei32) {
    int e = blockIdx.x * blockDim.x + threadIdx.x;
    if (e >= Ee) return;
    int r, c;
    load_edge(ei32, e, r, c);
    if (r != c) {
        int pos = atomicAdd(&g_cursor[c], 1);
        pos = min(max(pos, 0), Ee - 1);
        g_src[pos] = r;
        g_wn[pos]  = g_dinv[r] * g_dinv[c];
    }
}

__global__ void k_sortseg() {
    int n = blockIdx.x * blockDim.x + threadIdx.x;
    if (n >= Nn) return;
    int e0 = g_rowptr[n], e1 = g_rowptr[n + 1];
    for (int i = e0 + 1; i < e1; i++) {
        int s = g_src[i]; float w = g_wn[i];
        int j = i - 1;
        while (j >= e0 && g_src[j] > s) {
            g_src[j + 1] = g_src[j]; g_wn[j + 1] = g_wn[j]; j--;
        }
        g_src[j + 1] = s; g_wn[j + 1] = w;
    }
}

// ---------------- fp32 -> bf16 hi/lo split conversions ----------------
__global__ void k_convA(const float* __restrict__ A) {
    long long i = (long long)blockIdx.x * blockDim.x + threadIdx.x;
    if (i >= (long long)Nn * KP1) return;
    int row = (int)(i >> 9), col = (int)(i & 511);
    float v = (col < INC) ? A[(size_t)row * INC + col] : 0.f;
    __nv_bfloat16 h = __float2bfloat16(v);
    g_Ah[i] = h;
    g_Al[i] = __float2bfloat16(v - __bfloat162float(h));
}

__global__ void k_convW1(const float* __restrict__ W) {
    int i = blockIdx.x * blockDim.x + threadIdx.x;
    if (i >= HIDC * KP1) return;
    int row = i >> 9, col = i & 511;
    float v = (col < INC) ? W[(size_t)row * INC + col] : 0.f;
    __nv_bfloat16 h = __float2bfloat16(v);
    g_W1h[i] = h;
    g_W1l[i] = __float2bfloat16(v - __bfloat162float(h));
}

__global__ void k_convW2(const float* __restrict__ W) {
    int i = blockIdx.x * blockDim.x + threadIdx.x;
    if (i >= OUTC * HIDC) return;
    float v = W[i];
    __nv_bfloat16 h = __float2bfloat16(v);
    g_W2h[i] = h;
    g_W2l[i] = __float2bfloat16(v - __bfloat162float(h));
}

// ---------------- bf16-split tensor-core GEMM ----------------
// C[m,n] = sum_k A[m,k]*B[n,k], computed as Ah*Bh + Ah*Bl + Al*Bh (fp32 accum).
// BM=128, BK=32, 8 warps (4 m-warps x 2 n-warps), warp tile 32 x (BN/2).
// MODE 0: A=g_Ah/g_Al, B=g_W1h/g_W1l, Kd=512, BN=128, epi=relu+split->g_Hh/g_Hl
// MODE 1: A=g_Hh/g_Hl, B=g_W2h/g_W2l, Kd=256, BN=64,  epi=+bias->g_Xa fp32
__device__ __forceinline__ void mma16816(float c[4], const unsigned a[4], const unsigned b[2]) {
    asm volatile(
        "mma.sync.aligned.m16n8k16.row.col.f32.bf16.bf16.f32 "
        "{%0,%1,%2,%3}, {%4,%5,%6,%7}, {%8,%9}, {%0,%1,%2,%3};"
        : "+f"(c[0]), "+f"(c[1]), "+f"(c[2]), "+f"(c[3])
        : "r"(a[0]), "r"(a[1]), "r"(a[2]), "r"(a[3]), "r"(b[0]), "r"(b[1]));
}

template <int MODE>
__global__ __launch_bounds__(256)
void k_mma(const float* __restrict__ bias, int M)
{
    constexpr int BN = (MODE == 0) ? 128 : 64;
    constexpr int Kd = (MODE == 0) ? KP1 : HIDC;
    constexpr int NS = BN / 16;          // n-subtiles per warp (8 or 4)
    constexpr int ST = 40;               // smem k-stride (32 + 8 pad), 80B rows

    const __nv_bfloat16* Ah = (MODE == 0) ? g_Ah  : g_Hh;
    const __nv_bfloat16* Al = (MODE == 0) ? g_Al  : g_Hl;
    const __nv_bfloat16* Bh = (MODE == 0) ? g_W1h : g_W2h;
    const __nv_bfloat16* Bl = (MODE == 0) ? g_W1l : g_W2l;

    __shared__ __align__(16) __nv_bfloat16 sAh[128][ST];
    __shared__ __align__(16) __nv_bfloat16 sAl[128][ST];
    __shared__ __align__(16) __nv_bfloat16 sBh[BN][ST];
    __shared__ __align__(16) __nv_bfloat16 sBl[BN][ST];

    const int tid  = threadIdx.x;
    const int warp = tid >> 5;
    const int lane = tid & 31;
    const int grp  = lane >> 2;    // 0..7
    const int t4   = lane & 3;     // 0..3
    const int wm   = warp >> 1;    // 0..3
    const int wn   = warp & 1;     // 0..1
    const int m0   = blockIdx.x * 128;
    const int n0   = blockIdx.y * BN;

    float acc[2][NS][4];
    #pragma unroll
    for (int mi = 0; mi < 2; mi++)
        #pragma unroll
        for (int ni = 0; ni < NS; ni++)
            #pragma unroll
            for (int j = 0; j < 4; j++) acc[mi][ni][j] = 0.f;

    const uint4 zero4 = make_uint4(0, 0, 0, 0);

    for (int k0 = 0; k0 < Kd; k0 += 32) {
        __syncthreads();
        // A tiles: 128 x 32 bf16 = 8KB each -> 2 uint4 per thread per array
        #pragma unroll
        for (int i = 0; i < 2; i++) {
            int id  = tid + i * 256;
            int row = id >> 2;
            int cc  = id & 3;
            size_t goff = (size_t)(m0 + row) * Kd + k0 + cc * 8;
            bool ok = (m0 + row) < M;
            *reinterpret_cast<uint4*>(&sAh[row][cc * 8]) =
                ok ? *reinterpret_cast<const uint4*>(Ah + goff) : zero4;
            *reinterpret_cast<uint4*>(&sAl[row][cc * 8]) =
                ok ? *reinterpret_cast<const uint4*>(Al + goff) : zero4;
        }
        // B tiles: BN x 32
        #pragma unroll
        for (int i = 0; i < BN / 64; i++) {
            int id  = tid + i * 256;
            int row = id >> 2;
            int cc  = id & 3;
            size_t goff = (size_t)(n0 + row) * Kd + k0 + cc * 8;
            *reinterpret_cast<uint4*>(&sBh[row][cc * 8]) =
                *reinterpret_cast<const uint4*>(Bh + goff);
            *reinterpret_cast<uint4*>(&sBl[row][cc * 8]) =
                *reinterpret_cast<const uint4*>(Bl + goff);
        }
        __syncthreads();

        #pragma unroll
        for (int ks = 0; ks < 2; ks++) {
            const int kk = ks * 16;
            unsigned ah[2][4], al[2][4];
            #pragma unroll
            for (int mi = 0; mi < 2; mi++) {
                int r0 = wm * 32 + mi * 16 + grp;
                ah[mi][0] = *reinterpret_cast<const unsigned*>(&sAh[r0    ][kk + 2 * t4    ]);
                ah[mi][1] = *reinterpret_cast<const unsigned*>(&sAh[r0 + 8][kk + 2 * t4    ]);
                ah[mi][2] = *reinterpret_cast<const unsigned*>(&sAh[r0    ][kk + 2 * t4 + 8]);
                ah[mi][3] = *reinterpret_cast<const unsigned*>(&sAh[r0 + 8][kk + 2 * t4 + 8]);
                al[mi][0] = *reinterpret_cast<const unsigned*>(&sAl[r0    ][kk + 2 * t4    ]);
                al[mi][1] = *reinterpret_cast<const unsigned*>(&sAl[r0 + 8][kk + 2 * t4    ]);
                al[mi][2] = *reinterpret_cast<const unsigned*>(&sAl[r0    ][kk + 2 * t4 + 8]);
                al[mi][3] = *reinterpret_cast<const unsigned*>(&sAl[r0 + 8][kk + 2 * t4 + 8]);
            }
            #pragma unroll
            for (int ni = 0; ni < NS; ni++) {
                int nr = wn * (BN / 2) + ni * 8 + grp;
                unsigned bh[2], bl[2];
                bh[0] = *reinterpret_cast<const unsigned*>(&sBh[nr][kk + 2 * t4    ]);
                bh[1] = *reinterpret_cast<const unsigned*>(&sBh[nr][kk + 2 * t4 + 8]);
                bl[0] = *reinterpret_cast<const unsigned*>(&sBl[nr][kk + 2 * t4    ]);
                bl[1] = *reinterpret_cast<const unsigned*>(&sBl[nr][kk + 2 * t4 + 8]);
                mma16816(acc[0][ni], ah[0], bh);
                mma16816(acc[1][ni], ah[1], bh);
                mma16816(acc[0][ni], ah[0], bl);
                mma16816(acc[1][ni], ah[1], bl);
                mma16816(acc[0][ni], al[0], bh);
                mma16816(acc[1][ni], al[1], bh);
            }
        }
    }

    // epilogue
    #pragma unroll
    for (int mi = 0; mi < 2; mi++) {
        #pragma unroll
        for (int ni = 0; ni < NS; ni++) {
            int n = n0 + wn * (BN / 2) + ni * 8 + 2 * t4;
            float bb0 = bias[n], bb1 = bias[n + 1];
            #pragma unroll
            for (int half = 0; half < 2; half++) {
                int r = m0 + wm * 32 + mi * 16 + grp + half * 8;
                if (r >= M) continue;
                float v0 = acc[mi][ni][half * 2 + 0] + bb0;
                float v1 = acc[mi][ni][half * 2 + 1] + bb1;
                if (MODE == 0) {
                    v0 = fmaxf(v0, 0.f);
                    v1 = fmaxf(v1, 0.f);
                    __nv_bfloat16 h0 = __float2bfloat16(v0);
                    __nv_bfloat16 h1 = __float2bfloat16(v1);
                    __nv_bfloat16 l0 = __float2bfloat16(v0 - __bfloat162float(h0));
                    __nv_bfloat16 l1 = __float2bfloat16(v1 - __bfloat162float(h1));
                    __nv_bfloat162 hp; hp.x = h0; hp.y = h1;
                    __nv_bfloat162 lp; lp.x = l0; lp.y = l1;
                    *reinterpret_cast<__nv_bfloat162*>(&g_Hh[(size_t)r * HIDC + n]) = hp;
                    *reinterpret_cast<__nv_bfloat162*>(&g_Hl[(size_t)r * HIDC + n]) = lp;
                } else {
                    *reinterpret_cast<float2*>(&g_Xa[(size_t)r * OUTC + n]) =
                        make_float2(v0, v1);
                }
            }
        }
    }
}

// ---------------- hop-0 combine: out[n] = sigmoid(x0·pw + pb) * x0 ----------------
__global__ __launch_bounds__(256)
void k_combine0(const float* __restrict__ pw, const float* __restrict__ pb,
                float* __restrict__ out)
{
    int gw = (blockIdx.x * blockDim.x + threadIdx.x) >> 5;
    if (gw >= Nn) return;
    int lane = threadIdx.x & 31;
    const float2* x = reinterpret_cast<const float2*>(g_Xa);
    float2 v = x[gw * 32 + lane];
    float t = v.x * pw[2 * lane] + v.y * pw[2 * lane + 1];
    #pragma unroll
    for (int o = 16; o; o >>= 1) t += __shfl_xor_sync(0xffffffffu, t, o);
    float s = 1.f / (1.f + expf(-(t + pb[0])));
    reinterpret_cast<float2*>(out)[gw * 32 + lane] = make_float2(s * v.x, s * v.y);
}

// ---------------- fused propagation + attention-combine ----------------
__global__ __launch_bounds__(256)
void k_prop(int dir, const float* __restrict__ pw, const float* __restrict__ pb,
            float* __restrict__ out)
{
    int gw = (blockIdx.x * blockDim.x + threadIdx.x) >> 5;
    if (gw >= Nn) return;
    int lane = threadIdx.x & 31;
    const float2* xin = reinterpret_cast<const float2*>(dir ? g_Xb : g_Xa);
    float2*      xout = reinterpret_cast<float2*>(dir ? g_Xa : g_Xb);

    float d  = g_dinv[gw];
    float sw = d * d;
    float2 v = xin[gw * 32 + lane];
    float ax = sw * v.x;
    float ay = sw * v.y;

    int e  = g_rowptr[gw];
    int e1 = g_rowptr[gw + 1];
    for (; e + 4 <= e1; e += 4) {
        int   s0 = g_src[e], s1 = g_src[e + 1], s2 = g_src[e + 2], s3 = g_src[e + 3];
        float w0 = g_wn[e],  w1 = g_wn[e + 1],  w2 = g_wn[e + 2],  w3 = g_wn[e + 3];
        float2 p0 = xin[s0 * 32 + lane];
        float2 p1 = xin[s1 * 32 + lane];
        float2 p2 = xin[s2 * 32 + lane];
        float2 p3 = xin[s3 * 32 + lane];
        ax = fmaf(w0, p0.x, ax); ay = fmaf(w0, p0.y, ay);
        ax = fmaf(w1, p1.x, ax); ay = fmaf(w1, p1.y, ay);
        ax = fmaf(w2, p2.x, ax); ay = fmaf(w2, p2.y, ay);
        ax = fmaf(w3, p3.x, ax); ay = fmaf(w3, p3.y, ay);
    }
    for (; e < e1; e++) {
        int s = g_src[e]; float w = g_wn[e];
        float2 p = xin[s * 32 + lane];
        ax = fmaf(w, p.x, ax); ay = fmaf(w, p.y, ay);
    }

    xout[gw * 32 + lane] = make_float2(ax, ay);

    float t = ax * pw[2 * lane] + ay * pw[2 * lane + 1];
    #pragma unroll
    for (int o = 16; o; o >>= 1) t += __shfl_xor_sync(0xffffffffu, t, o);
    float s = 1.f / (1.f + expf(-(t + pb[0])));

    float2* op = reinterpret_cast<float2*>(out) + gw * 32 + lane;
    float2 cur = *op;
    cur.x += s * ax;
    cur.y += s * ay;
    *op = cur;
}

// ---------------- launch ----------------
extern "C" void kernel_launch(void* const* d_in, const int* in_sizes, int n_in,
                              void* d_out, int out_size)
{
    const float* node_feat = (const float*)d_in[0];
    const int*   ei32      = (const int*)d_in[1];
    const float* W1        = (const float*)d_in[2];
    const float* b1        = (const float*)d_in[3];
    const float* W2        = (const float*)d_in[4];
    const float* b2        = (const float*)d_in[5];
    const float* pw        = (const float*)d_in[6];
    const float* pb        = (const float*)d_in[7];
    float*       out       = (float*)d_out;

    const int TB = 256;
    int gN = (Nn + TB - 1) / TB;
    int gE = (Ee + TB - 1) / TB;
    int gW = (Nn * 32 + TB - 1) / TB;

    // conversions (independent of CSR)
    long long nA = (long long)Nn * KP1;
    k_convA<<<(unsigned)((nA + TB - 1) / TB), TB>>>(node_feat);
    k_convW1<<<(HIDC * KP1 + TB - 1) / TB, TB>>>(W1);
    k_convW2<<<(OUTC * HIDC + TB - 1) / TB, TB>>>(W2);

    // edge dtype detection + CSR build (deterministic after k_sortseg)
    k_detect<<<1, 1>>>(ei32);
    k_zero_cnt<<<gN, TB>>>();
    k_count<<<gE, TB>>>(ei32);
    k_dinv<<<gN, TB>>>();
    k_scan1<<<NB_SCAN, 1024>>>();
    k_scan2<<<1, 1>>>();
    k_scan3<<<NB_SCAN, 1024>>>();
    k_fill<<<gE, TB>>>(ei32);
    k_sortseg<<<gN, TB>>>();

    // MLP on tensor cores (bf16-split, fp32 accumulate)
    dim3 g1((Nn + 127) / 128, HIDC / 128);
    k_mma<0><<<g1, 256>>>(b1, Nn);
    dim3 g2((Nn + 127) / 128, 1);
    k_mma<1><<<g2, 256>>>(b2, Nn);

    // hop 0 combine, then K fused propagate+combine steps
    k_combine0<<<gW, TB>>>(pw, pb, out);
    for (int k = 0; k < KHOP; k++)
        k_prop<<<gW, TB>>>(k & 1, pw, pb, out);
}